// round 12
// baseline (speedup 1.0000x reference)
#include <cuda_runtime.h>
#include <cuda_bf16.h>
#include <cstdint>

// ==========================================================================
// Scratch:
//  g_wscr: pre-split bf16 hi/lo weights, row-major [K][256] per plane.
//    w1 stage bases {0, 131072, 393216} (elements), lo plane at +K*256.
//    w2 stage s: 917504 + s*131072, lo at +65536.
//  g_xscr: gathered A-chunk records, 4096B each:
//    [hi plane 32 rows x 64B][lo plane 32 rows x 64B], row = tile-local m.
//    Stage bases (bytes): {0, 4194304, 12582912}; rec = base + (tile*nch+ch)*4096.
//  Flags (zero-init, self-cleaning each launch):
//    g_rflag[7168]: per gather record; producer sets 1, unique consumer resets.
//    g_wflag[80] / g_wcons[80]: per weight chunk; 128 consumers count, last resets.
//    Weight chunk flag idx: w1: {0,8,24}[s]+c ; w2: 56 + s*8 + c.
// ==========================================================================
__device__ __align__(16) __nv_bfloat16 g_wscr[1310720];
__device__ __align__(16) char g_xscr[29360128];
__device__ int g_rflag[7168];
__device__ int g_wflag[80];
__device__ int g_wcons[80];

// ---------------- PTX helpers (baseline sm_80+ PTX only) ----------------
__device__ __forceinline__ uint32_t s2u(const void* p) {
    return (uint32_t)__cvta_generic_to_shared(p);
}
__device__ __forceinline__ void ldsm4(uint32_t* r, uint32_t a) {
    asm volatile("ldmatrix.sync.aligned.m8n8.x4.shared.b16 {%0,%1,%2,%3}, [%4];"
                 : "=r"(r[0]), "=r"(r[1]), "=r"(r[2]), "=r"(r[3]) : "r"(a));
}
__device__ __forceinline__ void ldsm4t(uint32_t* r, uint32_t a) {
    asm volatile("ldmatrix.sync.aligned.m8n8.x4.trans.shared.b16 {%0,%1,%2,%3}, [%4];"
                 : "=r"(r[0]), "=r"(r[1]), "=r"(r[2]), "=r"(r[3]) : "r"(a));
}
__device__ __forceinline__ void mma_bf16(float* d, const uint32_t* a,
                                         uint32_t b0, uint32_t b1) {
    asm volatile(
        "mma.sync.aligned.m16n8k16.row.col.f32.bf16.bf16.f32 "
        "{%0,%1,%2,%3}, {%4,%5,%6,%7}, {%8,%9}, {%0,%1,%2,%3};"
        : "+f"(d[0]), "+f"(d[1]), "+f"(d[2]), "+f"(d[3])
        : "r"(a[0]), "r"(a[1]), "r"(a[2]), "r"(a[3]), "r"(b0), "r"(b1));
}
__device__ __forceinline__ void cpa16(uint32_t dst, const void* src) {
    asm volatile("cp.async.cg.shared.global [%0], [%1], 16;" :: "r"(dst), "l"(src));
}
#define CPA_COMMIT() asm volatile("cp.async.commit_group;" ::: "memory")
#define CPA_WAIT1()  asm volatile("cp.async.wait_group 1;" ::: "memory")
#define CPA_WAIT0()  asm volatile("cp.async.wait_group 0;" ::: "memory")

__device__ __forceinline__ int ld_acq(const int* p) {
    int v;
    asm volatile("ld.acquire.gpu.global.b32 %0, [%1];" : "=r"(v) : "l"(p) : "memory");
    return v;
}
// All warps call; lane0 spins, warp converges after.
__device__ __forceinline__ void wait_flag(int* f) {
    if ((threadIdx.x & 31) == 0) {
        while (ld_acq(f) == 0) __nanosleep(128);
    }
    __syncwarp();
}
// tid0 only: count consumption of a weight chunk; 128th consumer resets.
__device__ __forceinline__ void wconsume(int idx) {
    int old = atomicAdd(&g_wcons[idx], 1);
    if (old == 127) {
        g_wflag[idx] = 0;
        atomicSub(&g_wcons[idx], 128);
    }
}

// ==========================================================================
struct AP {
    const float* feat[3];
    const void*  pid[3];
    const float* w1[3];
    const float* w2[3];
    const float* b1[3];
    const float* b2[3];
    float* out;
    int C[3];
    int HW[3];
};

// mma smem layout (A rows 80B padded; B/hidden rows 528B padded)
constexpr int ABUF    = 5120;
constexpr int OFF_A   = 0;
constexpr int OFF_B   = 10240;
constexpr int BPLANE  = 16896;
constexpr int BBUF    = 33792;
constexpr int OFF_H   = 77824;
constexpr int HPLANE  = 16896;
constexpr int OFF_PN  = 111616;
constexpr int SMEM_ALLOC = 112128;

__device__ __forceinline__ void mma_step(float acc[8][4], uint32_t aHi,
                                         uint32_t aLo, uint32_t bRow, int wn) {
    uint32_t ah[4], al[4];
    ldsm4(ah, aHi);
    ldsm4(al, aLo);
#pragma unroll
    for (int pr = 0; pr < 4; pr++) {
        uint32_t bh[4], bl[4];
        uint32_t bc = bRow + (uint32_t)(wn * 64 + pr * 16) * 2;
        ldsm4t(bh, bc);
        ldsm4t(bl, bc + BPLANE);
        mma_bf16(acc[pr * 2], ah, bh[0], bh[1]);
        mma_bf16(acc[pr * 2], ah, bl[0], bl[1]);
        mma_bf16(acc[pr * 2], al, bh[0], bh[1]);
        mma_bf16(acc[pr * 2 + 1], ah, bh[2], bh[3]);
        mma_bf16(acc[pr * 2 + 1], ah, bl[2], bl[3]);
        mma_bf16(acc[pr * 2 + 1], al, bh[2], bh[3]);
    }
}

__device__ __forceinline__ void issue_chunk1(uint32_t smb, int buf,
                                             const char* arec,
                                             const __nv_bfloat16* wsrc,
                                             long long Koff, int tid) {
    const uint32_t adst = smb + OFF_A + buf * ABUF;
    const uint32_t bdst = smb + OFF_B + buf * BBUF;
#pragma unroll
    for (int r = 0; r < 9; r++) {
        int i = r * 256 + tid;
        if (i < 256) {
            int pl = i >> 7, rw = (i >> 2) & 31, q = i & 3;
            cpa16(adst + pl * 2560 + rw * 80 + q * 16, arec + i * 16);
        } else {
            int j = i - 256;
            int pl = j >> 10, k = (j >> 5) & 31, cc = j & 31;
            cpa16(bdst + pl * BPLANE + k * 528 + cc * 16,
                  wsrc + pl * Koff + k * 256 + cc * 8);
        }
    }
}

__device__ __forceinline__ void issue_chunk2(uint32_t smb, int buf,
                                             const __nv_bfloat16* wsrc, int tid) {
    const uint32_t bdst = smb + OFF_B + buf * BBUF;
#pragma unroll
    for (int r = 0; r < 8; r++) {
        int j = r * 256 + tid;
        int pl = j >> 10, k = (j >> 5) & 31, cc = j & 31;
        cpa16(bdst + pl * BPLANE + k * 528 + cc * 16,
              wsrc + pl * 65536 + k * 256 + cc * 8);
    }
}

// ==========================================================================
// Fused kernel: bids [0,80) weight prep; bids >=80 interleaved 7 gather : 3 mma.
// ==========================================================================
__global__ __launch_bounds__(256, 2) void patch_fused(AP p) {
    extern __shared__ char sm[];
    const int bid = blockIdx.x;
    const int tid = threadIdx.x;

    // ======================= weight prep (one chunk per block) ============
    if (bid < 80) {
        int s, c;
        long long hioff, Koff2;
        const float* src;
        if (bid < 56) {
            if (bid < 8)       { s = 0; c = bid;      hioff = 0;      Koff2 = 65536; }
            else if (bid < 24) { s = 1; c = bid - 8;  hioff = 131072; Koff2 = 131072; }
            else               { s = 2; c = bid - 24; hioff = 393216; Koff2 = 262144; }
            src = p.w1[s];
        } else {
            int t = bid - 56;
            s = t >> 3; c = t & 7;
            hioff = 917504LL + (long long)s * 131072;
            Koff2 = 65536;
            src = p.w2[s];
        }
        const long long base = hioff + (long long)c * 8192;
        const float* sp = src + (long long)c * 8192;
#pragma unroll 8
        for (int it = 0; it < 32; it++) {
            int j = it * 256 + tid;
            float v = sp[j];
            __nv_bfloat16 hi = __float2bfloat16(v);
            __nv_bfloat16 lo = __float2bfloat16(v - __bfloat162float(hi));
            g_wscr[base + j]         = hi;
            g_wscr[base + Koff2 + j] = lo;
        }
        __threadfence();
        __syncthreads();
        if (tid == 0) atomicExch(&g_wflag[bid], 1);
        return;
    }

    const int u   = bid - 80;
    const int grp = u / 10;
    const int r10 = u % 10;

    // ======================= gather (warp per chunk, LPT s2-first) ========
    if (r10 < 7) {
        const int gi   = grp * 7 + r10;        // 0..895
        const int lane = tid & 31;
        const int f0   = gi * 8 + (tid >> 5);  // 0..7167, s2-first ordering
        int s, local;
        if (f0 < 4096)      { s = 2; local = f0; }
        else if (f0 < 6144) { s = 1; local = f0 - 4096; }
        else                { s = 0; local = f0 - 6144; }
        const int lognch = (s == 0) ? 3 : (s == 1) ? 4 : 5;
        const int nch    = 1 << lognch;
        const int tile   = local >> lognch;
        const int ch     = local & (nch - 1);
        const int rb     = (s == 0) ? 0 : (s == 1) ? 1024 : 3072;
        const long long xb = (s == 0) ? 0LL : (s == 1) ? 4194304LL : 12582912LL;

        const int C = p.C[s];
        const long long HW = p.HW[s];

        // warp-local int64 detection: all 128 qwords valid as indices <=> int64
        bool okq = true;
        {
            const long long* q = (const long long*)p.pid[s];
#pragma unroll
            for (int j = 0; j < 4; j++) {
                long long v = q[lane * 4 + j];
                okq &= (v >= 0 && v < HW);
            }
        }
        const int is64 = __all_sync(0xffffffffu, okq);

        const int m = tile * 32 + lane, b = m >> 8, pp = m & 255;
        long long spos = is64 ? ((const long long*)p.pid[s])[pp]
                              : (long long)((const int*)p.pid[s])[pp];
        const float* fp = p.feat[s] + (long long)b * C * HW + spos
                          + (long long)(ch << 5) * HW;

        float v[32];
#pragma unroll
        for (int kk = 0; kk < 32; kk++) v[kk] = __ldg(fp + (long long)kk * HW);

        char* rec = g_xscr + xb + (long long)(tile * nch + ch) * 4096 + lane * 64;
#pragma unroll
        for (int q = 0; q < 4; q++) {
            uint32_t hw_[4], lw_[4];
#pragma unroll
            for (int j = 0; j < 4; j++) {
                float a = v[q * 8 + j * 2], c2 = v[q * 8 + j * 2 + 1];
                __nv_bfloat16 ha = __float2bfloat16(a), hc = __float2bfloat16(c2);
                __nv_bfloat16 la = __float2bfloat16(a - __bfloat162float(ha));
                __nv_bfloat16 lc = __float2bfloat16(c2 - __bfloat162float(hc));
                hw_[j] = (uint32_t)(*(uint16_t*)&ha) | ((uint32_t)(*(uint16_t*)&hc) << 16);
                lw_[j] = (uint32_t)(*(uint16_t*)&la) | ((uint32_t)(*(uint16_t*)&lc) << 16);
            }
            *(uint4*)(rec + q * 16)        = make_uint4(hw_[0], hw_[1], hw_[2], hw_[3]);
            *(uint4*)(rec + 2048 + q * 16) = make_uint4(lw_[0], lw_[1], lw_[2], lw_[3]);
        }
        __threadfence();
        __syncwarp();
        if (lane == 0) atomicExch(&g_rflag[rb + local], 1);
        return;
    }

    // ======================= mma consumer (LPT s2-first) ==================
    const int mi = grp * 3 + (r10 - 7);  // 0..383
    int s, tile;
    if (mi < 128)      { s = 2; tile = mi; }
    else if (mi < 256) { s = 1; tile = mi - 128; }
    else               { s = 0; tile = mi - 256; }

    const int lane = tid & 31;
    const int wid  = tid >> 5;
    const int wm   = wid & 1;
    const int wn   = wid >> 1;
    const int ti   = lane & 3;
    const int g    = lane >> 2;

    const int m0  = tile * 32;
    const int C   = p.C[s];
    const int nch = C >> 5;

    const int rb        = (s == 0) ? 0 : (s == 1) ? 1024 : 3072;
    const int wb1       = (s == 0) ? 0 : (s == 1) ? 8 : 24;
    const int wb2       = 56 + s * 8;
    const long long xb  = (s == 0) ? 0LL : (s == 1) ? 4194304LL : 12582912LL;
    const char* xrec    = g_xscr + xb + (long long)tile * nch * 4096;
    const long long w1base = (s == 0) ? 0LL : (s == 1) ? 131072LL : 393216LL;
    const long long Koff   = (long long)C * 256;

    const uint32_t smb = s2u(sm);
    const uint32_t aFr = smb + OFF_A + (wm * 16 + (lane & 15)) * 80 + (lane >> 4) * 16;
    const uint32_t bFr = smb + OFF_B + (lane & 15) * 528 + (lane >> 4) * 16;

    float acc[8][4];
#pragma unroll
    for (int i = 0; i < 8; i++)
#pragma unroll
        for (int jj = 0; jj < 4; jj++) acc[i][jj] = 0.f;

    // ---------------- GEMM1 ----------------
    wait_flag(&g_rflag[rb + tile * nch + 0]);
    wait_flag(&g_wflag[wb1 + 0]);
    issue_chunk1(smb, 0, xrec, g_wscr + w1base, Koff, tid);
    CPA_COMMIT();

    for (int c = 0; c < nch; c++) {
        if (c + 1 < nch) {
            wait_flag(&g_rflag[rb + tile * nch + c + 1]);
            wait_flag(&g_wflag[wb1 + c + 1]);
            issue_chunk1(smb, (c + 1) & 1, xrec + (long long)(c + 1) * 4096,
                         g_wscr + w1base + (long long)(c + 1) * 8192, Koff, tid);
            CPA_COMMIT();
            CPA_WAIT1();
        } else {
            CPA_WAIT0();
        }
        __syncthreads();     // group(c) data visible to all
        if (tid == 0) {
            g_rflag[rb + tile * nch + c] = 0;   // unique consumer resets
            wconsume(wb1 + c);
        }
        uint32_t aHi = aFr + (c & 1) * ABUF;
        uint32_t bb  = bFr + (c & 1) * BBUF;
#pragma unroll
        for (int kk = 0; kk < 2; kk++)
            mma_step(acc, aHi + kk * 32, aHi + 2560 + kk * 32, bb + kk * 16 * 528, wn);
        __syncthreads();     // all done reading buf before reuse
    }

    // ---- GEMM2 chunk0 -> buf0 (nch even: buf0's last readers done) ----
    const long long w2base = 917504LL + (long long)s * 131072;
    wait_flag(&g_wflag[wb2]);
    issue_chunk2(smb, 0, g_wscr + w2base, tid);
    CPA_COMMIT();

    // ---------------- epilogue 1: relu + bias -> hidden hi/lo -------------
    {
        const float* __restrict__ b1 = p.b1[s];
        const int r0 = wm * 16 + g;
#pragma unroll
        for (int nf = 0; nf < 8; nf++) {
            int c0 = wn * 64 + nf * 8 + ti * 2;
            float ba = __ldg(b1 + c0), bbv = __ldg(b1 + c0 + 1);
            float v0 = fmaxf(acc[nf][0] + ba, 0.f);
            float v1 = fmaxf(acc[nf][1] + bbv, 0.f);
            float v2 = fmaxf(acc[nf][2] + ba, 0.f);
            float v3 = fmaxf(acc[nf][3] + bbv, 0.f);
            __nv_bfloat16 h0 = __float2bfloat16(v0), h1 = __float2bfloat16(v1);
            __nv_bfloat16 h2 = __float2bfloat16(v2), h3 = __float2bfloat16(v3);
            __nv_bfloat162 hi01; hi01.x = h0; hi01.y = h1;
            __nv_bfloat162 hi23; hi23.x = h2; hi23.y = h3;
            __nv_bfloat162 lo01, lo23;
            lo01.x = __float2bfloat16(v0 - __bfloat162float(h0));
            lo01.y = __float2bfloat16(v1 - __bfloat162float(h1));
            lo23.x = __float2bfloat16(v2 - __bfloat162float(h2));
            lo23.y = __float2bfloat16(v3 - __bfloat162float(h3));
            *(__nv_bfloat162*)(sm + OFF_H + r0 * 528 + c0 * 2)                = hi01;
            *(__nv_bfloat162*)(sm + OFF_H + (r0 + 8) * 528 + c0 * 2)          = hi23;
            *(__nv_bfloat162*)(sm + OFF_H + HPLANE + r0 * 528 + c0 * 2)       = lo01;
            *(__nv_bfloat162*)(sm + OFF_H + HPLANE + (r0 + 8) * 528 + c0 * 2) = lo23;
#pragma unroll
            for (int jj = 0; jj < 4; jj++) acc[nf][jj] = 0.f;
        }
    }

    // ---------------- GEMM2: K=256, 8 chunks ----------------
    const uint32_t aRow2 = smb + OFF_H + (wm * 16 + (lane & 15)) * 528 + (lane >> 4) * 16;
    for (int c2 = 0; c2 < 8; c2++) {
        if (c2 + 1 < 8) {
            wait_flag(&g_wflag[wb2 + c2 + 1]);
            issue_chunk2(smb, (c2 + 1) & 1,
                         g_wscr + w2base + (long long)(c2 + 1) * 8192, tid);
            CPA_COMMIT();
            CPA_WAIT1();
        } else {
            CPA_WAIT0();
        }
        __syncthreads();     // H + group(c2) visible
        if (tid == 0) wconsume(wb2 + c2);
        uint32_t bb = bFr + (c2 & 1) * BBUF;
#pragma unroll
        for (int kk = 0; kk < 2; kk++)
            mma_step(acc, aRow2 + c2 * 64 + kk * 32,
                     aRow2 + HPLANE + c2 * 64 + kk * 32, bb + kk * 16 * 528, wn);
        __syncthreads();
    }

    // ---------------- epilogue 2: bias, L2 norm, store ----------------
    {
        const float* __restrict__ b2 = p.b2[s];
        float b2a[8], b2b[8];
#pragma unroll
        for (int nf = 0; nf < 8; nf++) {
            int c0 = wn * 64 + nf * 8 + ti * 2;
            b2a[nf] = __ldg(b2 + c0);
            b2b[nf] = __ldg(b2 + c0 + 1);
        }
        float s0 = 0.f, s1 = 0.f;
#pragma unroll
        for (int nf = 0; nf < 8; nf++) {
            float v0 = acc[nf][0] + b2a[nf], v1 = acc[nf][1] + b2b[nf];
            float v2 = acc[nf][2] + b2a[nf], v3 = acc[nf][3] + b2b[nf];
            s0 += v0 * v0 + v1 * v1;
            s1 += v2 * v2 + v3 * v3;
        }
        s0 += __shfl_xor_sync(0xffffffffu, s0, 1);
        s0 += __shfl_xor_sync(0xffffffffu, s0, 2);
        s1 += __shfl_xor_sync(0xffffffffu, s1, 1);
        s1 += __shfl_xor_sync(0xffffffffu, s1, 2);
        float* pn = (float*)(sm + OFF_PN);
        const int r0 = wm * 16 + g;
        if (ti == 0) {
            pn[wn * 32 + r0]     = s0;
            pn[wn * 32 + r0 + 8] = s1;
        }
        __syncthreads();
        float t0 = pn[r0] + pn[32 + r0] + pn[64 + r0] + pn[96 + r0];
        float t1 = pn[r0 + 8] + pn[32 + r0 + 8] + pn[64 + r0 + 8] + pn[96 + r0 + 8];
        float sc0 = 1.f / (sqrtf(t0) + 1e-7f);
        float sc1 = 1.f / (sqrtf(t1) + 1e-7f);
        float* o0 = p.out + ((long long)s * 4096 + m0 + r0) * 256;
        float* o1 = o0 + 8 * 256;
#pragma unroll
        for (int nf = 0; nf < 8; nf++) {
            int c0 = wn * 64 + nf * 8 + ti * 2;
            float2 u0, u1;
            u0.x = (acc[nf][0] + b2a[nf]) * sc0;
            u0.y = (acc[nf][1] + b2b[nf]) * sc0;
            u1.x = (acc[nf][2] + b2a[nf]) * sc1;
            u1.y = (acc[nf][3] + b2b[nf]) * sc1;
            *(float2*)(o0 + c0) = u0;
            *(float2*)(o1 + c0) = u1;
        }
    }
}

// ==========================================================================
extern "C" void kernel_launch(void* const* d_in, const int* in_sizes, int n_in,
                              void* d_out, int out_size) {
    (void)n_in; (void)out_size;
    int fi[3], pi[3], w1i[3], b1i[3], w2i[3], b2i[3];
    if (in_sizes[1] == 256) {
        for (int s = 0; s < 3; s++) {  // dict order: feat,pid,w1,b1,w2,b2 per stage
            int b = 6 * s;
            fi[s] = b; pi[s] = b + 1; w1i[s] = b + 2;
            b1i[s] = b + 3; w2i[s] = b + 4; b2i[s] = b + 5;
        }
    } else {
        for (int s = 0; s < 3; s++) {  // signature order
            fi[s] = s; pi[s] = 3 + s;
            int b = 6 + 4 * s;
            w1i[s] = b; b1i[s] = b + 1; w2i[s] = b + 2; b2i[s] = b + 3;
        }
    }

    AP p;
    for (int s = 0; s < 3; s++) {
        p.feat[s] = (const float*)d_in[fi[s]];
        p.pid[s]  = (const void*)d_in[pi[s]];
        p.w1[s]   = (const float*)d_in[w1i[s]];
        p.w2[s]   = (const float*)d_in[w2i[s]];
        p.b1[s]   = (const float*)d_in[b1i[s]];
        p.b2[s]   = (const float*)d_in[b2i[s]];
        p.C[s]    = in_sizes[w1i[s]] / 256;
        p.HW[s]   = in_sizes[fi[s]] / (16 * p.C[s]);
    }
    p.out = (float*)d_out;

    static bool attr_set = false;
    if (!attr_set) {
        cudaFuncSetAttribute(patch_fused,
                             cudaFuncAttributeMaxDynamicSharedMemorySize,
                             SMEM_ALLOC);
        attr_set = true;
    }

    patch_fused<<<1360, 256, SMEM_ALLOC>>>(p);
}

// round 14
// speedup vs baseline: 1.8728x; 1.8728x over previous
#include <cuda_runtime.h>
#include <cuda_bf16.h>
#include <cstdint>

// ==========================================================================
// Scratch:
//  g_wscr: pre-split bf16 hi/lo weights, row-major [K][256] per plane.
//    w1 stage bases {0, 131072, 393216} (elements), lo plane at +K*256.
//    w2 stage s: 917504 + s*131072, lo at +65536.
//  g_xscr: gathered A-chunk records, 4096B each:
//    [hi plane 32 rows x 64B][lo plane 32 rows x 64B], row = tile-local m.
//    Stage bases (bytes): {0, 4194304, 12582912}; rec = base + (tile*nch+ch)*4096.
// ==========================================================================
__device__ __align__(16) __nv_bfloat16 g_wscr[1310720];
__device__ __align__(16) char g_xscr[29360128];

// ---------------- PTX helpers (baseline sm_80+ PTX only) ----------------
__device__ __forceinline__ uint32_t s2u(const void* p) {
    return (uint32_t)__cvta_generic_to_shared(p);
}
__device__ __forceinline__ void ldsm4(uint32_t* r, uint32_t a) {
    asm volatile("ldmatrix.sync.aligned.m8n8.x4.shared.b16 {%0,%1,%2,%3}, [%4];"
                 : "=r"(r[0]), "=r"(r[1]), "=r"(r[2]), "=r"(r[3]) : "r"(a));
}
__device__ __forceinline__ void ldsm4t(uint32_t* r, uint32_t a) {
    asm volatile("ldmatrix.sync.aligned.m8n8.x4.trans.shared.b16 {%0,%1,%2,%3}, [%4];"
                 : "=r"(r[0]), "=r"(r[1]), "=r"(r[2]), "=r"(r[3]) : "r"(a));
}
__device__ __forceinline__ void mma_bf16(float* d, const uint32_t* a,
                                         uint32_t b0, uint32_t b1) {
    asm volatile(
        "mma.sync.aligned.m16n8k16.row.col.f32.bf16.bf16.f32 "
        "{%0,%1,%2,%3}, {%4,%5,%6,%7}, {%8,%9}, {%0,%1,%2,%3};"
        : "+f"(d[0]), "+f"(d[1]), "+f"(d[2]), "+f"(d[3])
        : "r"(a[0]), "r"(a[1]), "r"(a[2]), "r"(a[3]), "r"(b0), "r"(b1));
}
__device__ __forceinline__ void cpa16(uint32_t dst, const void* src) {
    asm volatile("cp.async.cg.shared.global [%0], [%1], 16;" :: "r"(dst), "l"(src));
}
#define CPA_COMMIT() asm volatile("cp.async.commit_group;" ::: "memory")
#define CPA_WAIT1()  asm volatile("cp.async.wait_group 1;" ::: "memory")
#define CPA_WAIT0()  asm volatile("cp.async.wait_group 0;" ::: "memory")

// ==========================================================================
struct GP {
    const float* feat[3];
    const void*  pid[3];
    const float* w1[3];
    const float* w2[3];
    int C[3];
    int HW[3];
};

// Weight prep: fp32 -> bf16 hi/lo planes (64 blocks).
__global__ __launch_bounds__(256) void prep_w(GP g) {
    for (int idx = blockIdx.x * 256 + threadIdx.x; idx < 655360; idx += 64 * 256) {
        int s, j;
        const float* src;
        long long hioff, looff;
        if (idx < 458752) {
            if (idx < 65536)       { s = 0; j = idx;          hioff = 0;      looff = 65536; }
            else if (idx < 196608) { s = 1; j = idx - 65536;  hioff = 131072; looff = 262144; }
            else                   { s = 2; j = idx - 196608; hioff = 393216; looff = 655360; }
            src = g.w1[s];
        } else {
            int i = idx - 458752;
            s = i >> 16; j = i & 65535;
            src = g.w2[s];
            hioff = 917504LL + s * 131072;
            looff = hioff + 65536;
        }
        float v = src[j];
        __nv_bfloat16 hi = __float2bfloat16(v);
        __nv_bfloat16 lo = __float2bfloat16(v - __bfloat162float(hi));
        g_wscr[hioff + j] = hi;
        g_wscr[looff + j] = lo;
    }
}

// ==========================================================================
// Per-stage warp-per-chunk gather. Grid = (128*nch)/8 blocks x 8 warps.
// Warp: lane <-> tile row; 32 strided channel loads, bf16 hi/lo convert,
// coalesced 64B-row record store. No block syncs, no smem.
// ==========================================================================
__global__ __launch_bounds__(256, 4) void gather_wpc(GP g, int s) {
    const int tid  = threadIdx.x;
    const int lane = tid & 31;
    const int lognch = (s == 0) ? 3 : (s == 1) ? 4 : 5;
    const int nch    = 1 << lognch;
    const int local  = blockIdx.x * 8 + (tid >> 5);
    const int tile   = local >> lognch;
    const int ch     = local & (nch - 1);
    const long long xb = (s == 0) ? 0LL : (s == 1) ? 4194304LL : 12582912LL;

    const int C = g.C[s];
    const long long HW = g.HW[s];

    // warp-local int64 detection: all 128 qwords valid as indices <=> int64
    bool okq = true;
    {
        const long long* q = (const long long*)g.pid[s];
#pragma unroll
        for (int j = 0; j < 4; j++) {
            long long v = q[lane * 4 + j];
            okq &= (v >= 0 && v < HW);
        }
    }
    const int is64 = __all_sync(0xffffffffu, okq);

    const int m = tile * 32 + lane, b = m >> 8, pp = m & 255;
    long long spos = is64 ? ((const long long*)g.pid[s])[pp]
                          : (long long)((const int*)g.pid[s])[pp];
    const float* fp = g.feat[s] + (long long)b * C * HW + spos
                      + (long long)(ch << 5) * HW;

    float v[32];
#pragma unroll
    for (int kk = 0; kk < 32; kk++) v[kk] = __ldg(fp + (long long)kk * HW);

    char* rec = g_xscr + xb + (long long)(tile * nch + ch) * 4096 + lane * 64;
#pragma unroll
    for (int q = 0; q < 4; q++) {
        uint32_t hw_[4], lw_[4];
#pragma unroll
        for (int j = 0; j < 4; j++) {
            float a = v[q * 8 + j * 2], c2 = v[q * 8 + j * 2 + 1];
            __nv_bfloat16 ha = __float2bfloat16(a), hc = __float2bfloat16(c2);
            __nv_bfloat16 la = __float2bfloat16(a - __bfloat162float(ha));
            __nv_bfloat16 lc = __float2bfloat16(c2 - __bfloat162float(hc));
            hw_[j] = (uint32_t)(*(uint16_t*)&ha) | ((uint32_t)(*(uint16_t*)&hc) << 16);
            lw_[j] = (uint32_t)(*(uint16_t*)&la) | ((uint32_t)(*(uint16_t*)&lc) << 16);
        }
        *(uint4*)(rec + q * 16)        = make_uint4(hw_[0], hw_[1], hw_[2], hw_[3]);
        *(uint4*)(rec + 2048 + q * 16) = make_uint4(lw_[0], lw_[1], lw_[2], lw_[3]);
    }
}

// ==========================================================================
// Per-stage GEMM kernel (128 blocks). MT=32 rows, KC=32, 8 warps (2M x 4N).
// ==========================================================================
struct MP {
    const float* b1[3];
    const float* b2[3];
    float* out;
    int C[3];
};

constexpr int ABUF    = 5120;
constexpr int OFF_A   = 0;
constexpr int OFF_B   = 10240;
constexpr int BPLANE  = 16896;
constexpr int BBUF    = 33792;
constexpr int OFF_H   = 77824;
constexpr int HPLANE  = 16896;
constexpr int OFF_PN  = 111616;
constexpr int SMEM_ALLOC = 112128;

__device__ __forceinline__ void mma_step(float acc[8][4], uint32_t aHi,
                                         uint32_t aLo, uint32_t bRow, int wn) {
    uint32_t ah[4], al[4];
    ldsm4(ah, aHi);
    ldsm4(al, aLo);
#pragma unroll
    for (int pr = 0; pr < 4; pr++) {
        uint32_t bh[4], bl[4];
        uint32_t bc = bRow + (uint32_t)(wn * 64 + pr * 16) * 2;
        ldsm4t(bh, bc);
        ldsm4t(bl, bc + BPLANE);
        mma_bf16(acc[pr * 2], ah, bh[0], bh[1]);
        mma_bf16(acc[pr * 2], ah, bl[0], bl[1]);
        mma_bf16(acc[pr * 2], al, bh[0], bh[1]);
        mma_bf16(acc[pr * 2 + 1], ah, bh[2], bh[3]);
        mma_bf16(acc[pr * 2 + 1], ah, bl[2], bl[3]);
        mma_bf16(acc[pr * 2 + 1], al, bh[2], bh[3]);
    }
}

__device__ __forceinline__ void issue_chunk1(uint32_t smb, int buf,
                                             const char* arec,
                                             const __nv_bfloat16* wsrc,
                                             long long Koff, int tid) {
    const uint32_t adst = smb + OFF_A + buf * ABUF;
    const uint32_t bdst = smb + OFF_B + buf * BBUF;
#pragma unroll
    for (int r = 0; r < 9; r++) {
        int i = r * 256 + tid;
        if (i < 256) {
            int pl = i >> 7, rw = (i >> 2) & 31, q = i & 3;
            cpa16(adst + pl * 2560 + rw * 80 + q * 16, arec + i * 16);
        } else {
            int j = i - 256;
            int pl = j >> 10, k = (j >> 5) & 31, cc = j & 31;
            cpa16(bdst + pl * BPLANE + k * 528 + cc * 16,
                  wsrc + pl * Koff + k * 256 + cc * 8);
        }
    }
}

__device__ __forceinline__ void issue_chunk2(uint32_t smb, int buf,
                                             const __nv_bfloat16* wsrc, int tid) {
    const uint32_t bdst = smb + OFF_B + buf * BBUF;
#pragma unroll
    for (int r = 0; r < 8; r++) {
        int j = r * 256 + tid;
        int pl = j >> 10, k = (j >> 5) & 31, cc = j & 31;
        cpa16(bdst + pl * BPLANE + k * 528 + cc * 16,
              wsrc + pl * 65536 + k * 256 + cc * 8);
    }
}

__global__ __launch_bounds__(256, 2) void patch_mlp_mma(MP p, int s) {
    extern __shared__ char sm[];
    const int tid  = threadIdx.x;
    const int lane = tid & 31;
    const int wid  = tid >> 5;
    const int wm   = wid & 1;
    const int wn   = wid >> 1;
    const int ti   = lane & 3;
    const int g    = lane >> 2;

    const int tile = blockIdx.x;
    const int m0   = tile * 32;
    const int C    = p.C[s];
    const int nch  = C >> 5;

    const long long xb     = (s == 0) ? 0LL : (s == 1) ? 4194304LL : 12582912LL;
    const char*     xrec   = g_xscr + xb + (long long)tile * nch * 4096;
    const long long w1base = (s == 0) ? 0LL : (s == 1) ? 131072LL : 393216LL;
    const long long Koff   = (long long)C * 256;

    const uint32_t smb = s2u(sm);
    const uint32_t aFr = smb + OFF_A + (wm * 16 + (lane & 15)) * 80 + (lane >> 4) * 16;
    const uint32_t bFr = smb + OFF_B + (lane & 15) * 528 + (lane >> 4) * 16;

    float acc[8][4];
#pragma unroll
    for (int i = 0; i < 8; i++)
#pragma unroll
        for (int jj = 0; jj < 4; jj++) acc[i][jj] = 0.f;

    // ---------------- GEMM1 ----------------
    issue_chunk1(smb, 0, xrec, g_wscr + w1base, Koff, tid);
    CPA_COMMIT();

    for (int c = 0; c < nch; c++) {
        if (c + 1 < nch) {
            issue_chunk1(smb, (c + 1) & 1, xrec + (long long)(c + 1) * 4096,
                         g_wscr + w1base + (long long)(c + 1) * 8192, Koff, tid);
            CPA_COMMIT();
            CPA_WAIT1();
        } else {
            CPA_WAIT0();
        }
        __syncthreads();
        uint32_t aHi = aFr + (c & 1) * ABUF;
        uint32_t bb  = bFr + (c & 1) * BBUF;
#pragma unroll
        for (int kk = 0; kk < 2; kk++)
            mma_step(acc, aHi + kk * 32, aHi + 2560 + kk * 32, bb + kk * 16 * 528, wn);
        __syncthreads();
    }

    // ---- GEMM2 chunk0 -> buf0 (nch even: buf0's last readers done) ----
    const long long w2base = 917504LL + (long long)s * 131072;
    issue_chunk2(smb, 0, g_wscr + w2base, tid);
    CPA_COMMIT();

    // ---------------- epilogue 1: relu + bias -> hidden hi/lo -------------
    {
        const float* __restrict__ b1 = p.b1[s];
        const int r0 = wm * 16 + g;
#pragma unroll
        for (int nf = 0; nf < 8; nf++) {
            int c0 = wn * 64 + nf * 8 + ti * 2;
            float ba = __ldg(b1 + c0), bbv = __ldg(b1 + c0 + 1);
            float v0 = fmaxf(acc[nf][0] + ba, 0.f);
            float v1 = fmaxf(acc[nf][1] + bbv, 0.f);
            float v2 = fmaxf(acc[nf][2] + ba, 0.f);
            float v3 = fmaxf(acc[nf][3] + bbv, 0.f);
            __nv_bfloat16 h0 = __float2bfloat16(v0), h1 = __float2bfloat16(v1);
            __nv_bfloat16 h2 = __float2bfloat16(v2), h3 = __float2bfloat16(v3);
            __nv_bfloat162 hi01; hi01.x = h0; hi01.y = h1;
            __nv_bfloat162 hi23; hi23.x = h2; hi23.y = h3;
            __nv_bfloat162 lo01, lo23;
            lo01.x = __float2bfloat16(v0 - __bfloat162float(h0));
            lo01.y = __float2bfloat16(v1 - __bfloat162float(h1));
            lo23.x = __float2bfloat16(v2 - __bfloat162float(h2));
            lo23.y = __float2bfloat16(v3 - __bfloat162float(h3));
            *(__nv_bfloat162*)(sm + OFF_H + r0 * 528 + c0 * 2)                = hi01;
            *(__nv_bfloat162*)(sm + OFF_H + (r0 + 8) * 528 + c0 * 2)          = hi23;
            *(__nv_bfloat162*)(sm + OFF_H + HPLANE + r0 * 528 + c0 * 2)       = lo01;
            *(__nv_bfloat162*)(sm + OFF_H + HPLANE + (r0 + 8) * 528 + c0 * 2) = lo23;
#pragma unroll
            for (int jj = 0; jj < 4; jj++) acc[nf][jj] = 0.f;
        }
    }

    // ---------------- GEMM2: K=256, 8 chunks ----------------
    const uint32_t aRow2 = smb + OFF_H + (wm * 16 + (lane & 15)) * 528 + (lane >> 4) * 16;
    for (int c2 = 0; c2 < 8; c2++) {
        if (c2 + 1 < 8) {
            issue_chunk2(smb, (c2 + 1) & 1,
                         g_wscr + w2base + (long long)(c2 + 1) * 8192, tid);
            CPA_COMMIT();
            CPA_WAIT1();
        } else {
            CPA_WAIT0();
        }
        __syncthreads();
        uint32_t bb = bFr + (c2 & 1) * BBUF;
#pragma unroll
        for (int kk = 0; kk < 2; kk++)
            mma_step(acc, aRow2 + c2 * 64 + kk * 32,
                     aRow2 + HPLANE + c2 * 64 + kk * 32, bb + kk * 16 * 528, wn);
        __syncthreads();
    }

    // ---------------- epilogue 2: bias, L2 norm, store ----------------
    {
        const float* __restrict__ b2 = p.b2[s];
        float b2a[8], b2b[8];
#pragma unroll
        for (int nf = 0; nf < 8; nf++) {
            int c0 = wn * 64 + nf * 8 + ti * 2;
            b2a[nf] = __ldg(b2 + c0);
            b2b[nf] = __ldg(b2 + c0 + 1);
        }
        float s0 = 0.f, s1 = 0.f;
#pragma unroll
        for (int nf = 0; nf < 8; nf++) {
            float v0 = acc[nf][0] + b2a[nf], v1 = acc[nf][1] + b2b[nf];
            float v2 = acc[nf][2] + b2a[nf], v3 = acc[nf][3] + b2b[nf];
            s0 += v0 * v0 + v1 * v1;
            s1 += v2 * v2 + v3 * v3;
        }
        s0 += __shfl_xor_sync(0xffffffffu, s0, 1);
        s0 += __shfl_xor_sync(0xffffffffu, s0, 2);
        s1 += __shfl_xor_sync(0xffffffffu, s1, 1);
        s1 += __shfl_xor_sync(0xffffffffu, s1, 2);
        float* pn = (float*)(sm + OFF_PN);
        const int r0 = wm * 16 + g;
        if (ti == 0) {
            pn[wn * 32 + r0]     = s0;
            pn[wn * 32 + r0 + 8] = s1;
        }
        __syncthreads();
        float t0 = pn[r0] + pn[32 + r0] + pn[64 + r0] + pn[96 + r0];
        float t1 = pn[r0 + 8] + pn[32 + r0 + 8] + pn[64 + r0 + 8] + pn[96 + r0 + 8];
        float sc0 = 1.f / (sqrtf(t0) + 1e-7f);
        float sc1 = 1.f / (sqrtf(t1) + 1e-7f);
        float* o0 = p.out + ((long long)s * 4096 + m0 + r0) * 256;
        float* o1 = o0 + 8 * 256;
#pragma unroll
        for (int nf = 0; nf < 8; nf++) {
            int c0 = wn * 64 + nf * 8 + ti * 2;
            float2 u0, u1;
            u0.x = (acc[nf][0] + b2a[nf]) * sc0;
            u0.y = (acc[nf][1] + b2b[nf]) * sc0;
            u1.x = (acc[nf][2] + b2a[nf]) * sc1;
            u1.y = (acc[nf][3] + b2b[nf]) * sc1;
            *(float2*)(o0 + c0) = u0;
            *(float2*)(o1 + c0) = u1;
        }
    }
}

// ==========================================================================
// Host DAG:
//   s0: prep; G2; ->e2
//   sA: |-e2; G1; ->e1; G0; ->e0
//   sB: |-e2; M2; ->eB
//   sC: |-e1; M1; ->eC
//   s0: |-e0; M0; |-eB; |-eC          (proper join for graph capture)
// ==========================================================================
extern "C" void kernel_launch(void* const* d_in, const int* in_sizes, int n_in,
                              void* d_out, int out_size) {
    (void)n_in; (void)out_size;
    int fi[3], pi[3], w1i[3], b1i[3], w2i[3], b2i[3];
    if (in_sizes[1] == 256) {
        for (int s = 0; s < 3; s++) {  // dict order: feat,pid,w1,b1,w2,b2 per stage
            int b = 6 * s;
            fi[s] = b; pi[s] = b + 1; w1i[s] = b + 2;
            b1i[s] = b + 3; w2i[s] = b + 4; b2i[s] = b + 5;
        }
    } else {
        for (int s = 0; s < 3; s++) {  // signature order
            fi[s] = s; pi[s] = 3 + s;
            int b = 6 + 4 * s;
            w1i[s] = b; b1i[s] = b + 1; w2i[s] = b + 2; b2i[s] = b + 3;
        }
    }

    GP gp;
    MP p;
    for (int s = 0; s < 3; s++) {
        gp.feat[s] = (const float*)d_in[fi[s]];
        gp.pid[s]  = (const void*)d_in[pi[s]];
        gp.w1[s]   = (const float*)d_in[w1i[s]];
        gp.w2[s]   = (const float*)d_in[w2i[s]];
        p.b1[s]    = (const float*)d_in[b1i[s]];
        p.b2[s]    = (const float*)d_in[b2i[s]];
        gp.C[s]    = in_sizes[w1i[s]] / 256;
        p.C[s]     = gp.C[s];
        gp.HW[s]   = in_sizes[fi[s]] / (16 * gp.C[s]);
    }
    p.out = (float*)d_out;

    static bool init_done = false;
    static cudaStream_t sA = nullptr, sB = nullptr, sC = nullptr;
    static cudaEvent_t e2, e1, e0, eB, eC;
    if (!init_done) {
        cudaFuncSetAttribute(patch_mlp_mma,
                             cudaFuncAttributeMaxDynamicSharedMemorySize,
                             SMEM_ALLOC);
        cudaStreamCreateWithFlags(&sA, cudaStreamNonBlocking);
        cudaStreamCreateWithFlags(&sB, cudaStreamNonBlocking);
        cudaStreamCreateWithFlags(&sC, cudaStreamNonBlocking);
        cudaEventCreateWithFlags(&e2, cudaEventDisableTiming);
        cudaEventCreateWithFlags(&e1, cudaEventDisableTiming);
        cudaEventCreateWithFlags(&e0, cudaEventDisableTiming);
        cudaEventCreateWithFlags(&eB, cudaEventDisableTiming);
        cudaEventCreateWithFlags(&eC, cudaEventDisableTiming);
        init_done = true;
    }

    // s0: weights + heaviest gather first
    prep_w<<<64, 256>>>(gp);
    gather_wpc<<<512, 256>>>(gp, 2);
    cudaEventRecord(e2, 0);

    // sA: remaining gathers
    cudaStreamWaitEvent(sA, e2, 0);
    gather_wpc<<<256, 256, 0, sA>>>(gp, 1);
    cudaEventRecord(e1, sA);
    gather_wpc<<<128, 256, 0, sA>>>(gp, 0);
    cudaEventRecord(e0, sA);

    // sB: M2 as soon as its data is ready (overlaps G1/G0/M1/M0)
    cudaStreamWaitEvent(sB, e2, 0);
    patch_mlp_mma<<<128, 256, SMEM_ALLOC, sB>>>(p, 2);
    cudaEventRecord(eB, sB);

    // sC: M1
    cudaStreamWaitEvent(sC, e1, 0);
    patch_mlp_mma<<<128, 256, SMEM_ALLOC, sC>>>(p, 1);
    cudaEventRecord(eC, sC);

    // s0: M0, then join everything
    cudaStreamWaitEvent(0, e0, 0);
    patch_mlp_mma<<<128, 256, SMEM_ALLOC>>>(p, 0);
    cudaStreamWaitEvent(0, eB, 0);
    cudaStreamWaitEvent(0, eC, 0);
}